// round 14
// baseline (speedup 1.0000x reference)
#include <cuda_runtime.h>

// InterConv: B=2048, F=39, E=64, C=64, P=741
// out[b, c*P + p] = relu( U[c][ii[p]] + V[c][jj[p]] ),  U = x@Wi^T + bias, V = x@Wj^T
//
// Two-kernel split:
//   A (uv_kernel):  per batch, compute U/V (R11 phases 0/1/1b) -> g_UV[b] (5248 f)
//   B (exp_kernel): stage g_UV[b] to smem (24 KB, 6 CTAs/SM), expansion + relu
//                   (R11 phase 2: row-paired register-cached tab, fused pairs)

#define FN 39
#define EN 64
#define CN 64
#define PN 741            // 39*38/2
#define OUTB (CN * PN)    // 47424 floats per batch
#define THREADS 256
#define BMAX 2048
#define UVF  5248         // floats per batch in g_UV: Uc[64][41] + Vc[64][41]

__device__ float g_UV[(long long)BMAX * UVF];   // 43 MB scratch

// packed fp32x2 FMA (Blackwell; exact fp32 semantics, 2x FFMA throughput)
#define FMA_F32X2(acc, a, b) \
    asm("fma.rn.f32x2 %0, %1, %2, %0;" : "+l"(acc) : "l"(a), "l"(b))

extern __shared__ float smem[];

// ======================= Kernel A: U/V GEMM ============================
// smem (floats): xs [0,2624)  Wi [2624,6976)  Wj [6976,11328)  (stride 68)
// overlay after phase 1: Uc [0,2624)  Vc [2624,5248)
#define A_SMEM_FLOATS 11328
#define A_SMEM_BYTES  (A_SMEM_FLOATS * 4)

__global__ void __launch_bounds__(THREADS, 4)
uv_kernel(const float* __restrict__ x,
          const float* __restrict__ W,
          const float* __restrict__ bias)
{
    const int tid = threadIdx.x;
    const long long b = blockIdx.x;

    // ---- Phase 0: stage x and W (float4) ---------------------------------
    {
        float4* xs4 = (float4*)smem;
        const float4* xb4 = (const float4*)(x + b * (long long)(FN * EN));
        #pragma unroll
        for (int it = 0; it < 3; it++) {
            int idx = tid + it * THREADS;
            if (idx < (FN * EN) / 4) xs4[idx] = xb4[idx];
        }
        if (tid < EN)                              // zero pad row f=39
            smem[FN * EN + tid] = 0.f;

        float4* Wi4 = (float4*)(smem + 2624);      // [c][17]
        float4* Wj4 = Wi4 + CN * 17;
        const float4* Wg4 = (const float4*)W;
        #pragma unroll
        for (int it = 0; it < 8; it++) {
            int idx = tid + it * THREADS;          // 2048 float4 total
            int c = idx >> 5, q = idx & 31;
            float4 w = Wg4[idx];
            if (q < 16) Wi4[c * 17 + q] = w;
            else        Wj4[c * 17 + (q - 16)] = w;
        }
    }
    __syncthreads();

    // ---- Phase 1: U = x @ Wi^T + b, V = x @ Wj^T  (f32x2, regs only) -----
    const int c  = tid & 63;
    const int fg = tid >> 6;

    unsigned long long au[10], av[10];
    #pragma unroll
    for (int k = 0; k < 10; k++) { au[k] = 0ull; av[k] = 0ull; }

    {
        const ulonglong2* xs2 = (const ulonglong2*)smem;             // [f][16]
        const ulonglong2* Wi2 = (const ulonglong2*)(smem + 2624);    // [c][17]
        const ulonglong2* Wj2 = Wi2 + CN * 17;

        #pragma unroll
        for (int e4 = 0; e4 < 16; e4++) {
            ulonglong2 wi = Wi2[c * 17 + e4];
            ulonglong2 wj = Wj2[c * 17 + e4];
            #pragma unroll
            for (int k = 0; k < 10; k++) {
                ulonglong2 xv = xs2[(fg + 4 * k) * 16 + e4];  // f=39 row is zeros
                FMA_F32X2(au[k], xv.x, wi.x);
                FMA_F32X2(au[k], xv.y, wi.y);
                FMA_F32X2(av[k], xv.x, wj.x);
                FMA_F32X2(av[k], xv.y, wj.y);
            }
        }
    }
    __syncthreads();   // all xs/W reads done; safe to overlay

    // ---- Phase 1b: write Uc/Vc (transposed, stride 41) into smem --------
    float* Uc = smem;                          // [c][41]
    float* Vc = smem + 2624;                   // [c][41]
    {
        const float bc = __ldg(bias + c);
        #pragma unroll
        for (int k = 0; k < 10; k++) {
            int f = fg + 4 * k;                // f<=39; f=39 lands in row pad
            float ulo = __uint_as_float((unsigned)au[k]);
            float uhi = __uint_as_float((unsigned)(au[k] >> 32));
            float vlo = __uint_as_float((unsigned)av[k]);
            float vhi = __uint_as_float((unsigned)(av[k] >> 32));
            Uc[c * 41 + f] = ulo + uhi + bc;   // bias folded into U
            Vc[c * 41 + f] = vlo + vhi;
        }
    }
    __syncthreads();

    // ---- Phase 1c: dump U/V to gmem (coalesced float4) ------------------
    {
        float4* dst = (float4*)(g_UV + b * (long long)UVF);
        const float4* src = (const float4*)smem;
        #pragma unroll
        for (int it = 0; it < 6; it++) {
            int idx = tid + it * THREADS;      // 1312 float4 total
            if (idx < UVF / 4) dst[idx] = src[idx];
        }
    }
}

// ======================= Kernel B: expansion ===========================
// smem (floats): Uc [0,2624)  Vc [2624,5248)  tab [5248,5992)  -> 23.97 KB
#define B_SMEM_FLOATS 5992
#define B_SMEM_BYTES  (B_SMEM_FLOATS * 4)

__global__ void __launch_bounds__(THREADS, 6)
exp_kernel(float* __restrict__ out)
{
    const int tid = threadIdx.x;
    const long long b = blockIdx.x;
    unsigned* tab = (unsigned*)(smem + UVF);

    // ---- Phase 0: stage U/V; build tab behind the LDGs -------------------
    {
        float4* dst = (float4*)smem;
        const float4* src = (const float4*)(g_UV + b * (long long)UVF);
        #pragma unroll
        for (int it = 0; it < 6; it++) {
            int idx = tid + it * THREADS;      // 1312 float4 total
            if (idx < UVF / 4) dst[idx] = src[idx];
        }
        // pair table (np.triu_indices(F,1) row-major): byte offsets i*4 | j*4<<16
        for (int p = tid; p < PN; p += THREADS) {
            int i = 0, rem = p;
            while (rem >= FN - 1 - i) { rem -= FN - 1 - i; i++; }
            int j = i + 1 + rem;
            tab[p] = (unsigned)(i * 4) | ((unsigned)(j * 4) << 16);
        }
    }
    __syncthreads();

    const float* Uc = smem;                    // [c][41]
    const float* Vc = smem + 2624;             // [c][41]
    const int lane = tid & 31;
    const int wrp  = tid >> 5;
    float* outb = out + b * (long long)OUTB;

    // ---- Expansion + relu, fused row pairs, register-cached tab ----------
    #pragma unroll 1
    for (int k = 0; k < 4; k++) {
        const int r  = wrp * 4 + k;           // rows r and r+32 share p0
        const int p0 = (27 * r) & 31;

        // preload the 22-entry aligned tab window into registers
        unsigned tw[22];
        {
            const unsigned* tb = tab + p0 + lane;
            #pragma unroll
            for (int it = 0; it < 22; it++) tw[it] = tb[it * 32];
        }

        const char* bu0 = (const char*)(Uc + r * 41);
        const char* bv0 = (const char*)(Vc + r * 41);
        const char* bu1 = (const char*)(Uc + (r + 32) * 41);
        const char* bv1 = (const char*)(Vc + (r + 32) * 41);
        float* po0 = outb + r * PN;
        float* po1 = outb + (r + 32) * PN;

        // head: p in [0, p0), both rows
        if (lane < p0) {
            unsigned t = tab[lane];
            float u0 = *(const float*)(bu0 + (t & 0xFFFFu));
            float v0 = *(const float*)(bv0 + (t >> 16));
            float u1 = *(const float*)(bu1 + (t & 0xFFFFu));
            float v1 = *(const float*)(bv1 + (t >> 16));
            __stcs(po0 + lane, fmaxf(u0 + v0, 0.f));
            __stcs(po1 + lane, fmaxf(u1 + v1, 0.f));
        }

        // main: 22 warp-iterations, both rows per iteration (2 indep chains)
        float* q0 = po0 + p0;
        float* q1 = po1 + p0;
        #pragma unroll
        for (int it = 0; it < 22; it++) {
            unsigned t = tw[it];
            unsigned ui = t & 0xFFFFu, vi = t >> 16;
            float u0 = *(const float*)(bu0 + ui);
            float v0 = *(const float*)(bv0 + vi);
            float u1 = *(const float*)(bu1 + ui);
            float v1 = *(const float*)(bv1 + vi);
            __stcs(q0 + it * 32 + lane, fmaxf(u0 + v0, 0.f));
            __stcs(q1 + it * 32 + lane, fmaxf(u1 + v1, 0.f));
        }

        // tail: p in [p0+704, 741), both rows
        int p = p0 + 704 + lane;
        #pragma unroll
        for (int tt = 0; tt < 2; tt++) {
            if (p < PN) {
                unsigned t = tab[p];
                float u0 = *(const float*)(bu0 + (t & 0xFFFFu));
                float v0 = *(const float*)(bv0 + (t >> 16));
                float u1 = *(const float*)(bu1 + (t & 0xFFFFu));
                float v1 = *(const float*)(bv1 + (t >> 16));
                __stcs(po0 + p, fmaxf(u0 + v0, 0.f));
                __stcs(po1 + p, fmaxf(u1 + v1, 0.f));
            }
            p += 32;
        }
    }
}

extern "C" void kernel_launch(void* const* d_in, const int* in_sizes, int n_in,
                              void* d_out, int out_size)
{
    const float* x    = (const float*)d_in[0];
    const float* W    = (const float*)d_in[1];
    const float* bias = (const float*)d_in[2];
    float* out = (float*)d_out;

    const int B = in_sizes[0] / (FN * EN);   // 2048

    cudaFuncSetAttribute(uv_kernel,
                         cudaFuncAttributeMaxDynamicSharedMemorySize, A_SMEM_BYTES);
    cudaFuncSetAttribute(exp_kernel,
                         cudaFuncAttributeMaxDynamicSharedMemorySize, B_SMEM_BYTES);

    uv_kernel<<<B, THREADS, A_SMEM_BYTES>>>(x, W, bias);
    exp_kernel<<<B, THREADS, B_SMEM_BYTES>>>(out);
}

// round 15
// speedup vs baseline: 1.1876x; 1.1876x over previous
#include <cuda_runtime.h>

// InterConv: B=2048, F=39, E=64, C=64, P=741
// out[b, c*P + p] = relu( U[c][ii[p]] + V[c][jj[p]] ),  U = x@Wi^T + bias, V = x@Wj^T
//
// Persistent kernel: grid = 4*numSMs CTAs, each pulls batches from a global
// atomic queue (kills the 3.46-wave tail quantization of the 2048-CTA launch).
// Per-batch body is identical to the 86.1us R11 kernel.
//
// smem (floats), 48.3 KB -> 4 CTAs/SM:
//   per batch: xs [0,2624)   Wi [2624,6976)  Wj [6976,11328)   (stride 68)
//   tab (dedicated, built once per CTA): [11328,12072)
//   phase-2 overlay: Uc [0,2624)  Vc [2624,5248)

#define FN 39
#define EN 64
#define CN 64
#define PN 741            // 39*38/2
#define OUTB (CN * PN)    // 47424 floats per batch
#define THREADS 256

#define A_OFF   0
#define B_OFF   2624
#define TAB_OFF 11328
#define SMEM_FLOATS 12072
#define SMEM_BYTES  (SMEM_FLOATS * 4)   // 48288

// packed fp32x2 FMA (Blackwell; exact fp32 semantics, 2x FFMA throughput)
#define FMA_F32X2(acc, a, b) \
    asm("fma.rn.f32x2 %0, %1, %2, %0;" : "+l"(acc) : "l"(a), "l"(b))

__device__ unsigned g_ctr;

__global__ void reset_ctr() { g_ctr = 0; }

extern __shared__ float smem[];

__global__ void __launch_bounds__(THREADS, 4)
interconv_kernel(const float* __restrict__ x,
                 const float* __restrict__ W,
                 const float* __restrict__ bias,
                 float* __restrict__ out,
                 int B)
{
    const int tid  = threadIdx.x;
    const int lane = tid & 31;
    const int wrp  = tid >> 5;
    unsigned* tab = (unsigned*)(smem + TAB_OFF);
    __shared__ unsigned s_b;

    // ---- tab build: once per CTA (np.triu_indices(F,1) row-major) --------
    for (int p = tid; p < PN; p += THREADS) {
        int i = 0, rem = p;
        while (rem >= FN - 1 - i) { rem -= FN - 1 - i; i++; }
        int j = i + 1 + rem;
        tab[p] = (unsigned)(i * 4) | ((unsigned)(j * 4) << 16);
    }

    for (;;) {
        // grab next batch (sync also protects smem reuse across iterations)
        __syncthreads();
        if (tid == 0) s_b = atomicAdd(&g_ctr, 1u);
        __syncthreads();
        const unsigned bu = s_b;
        if (bu >= (unsigned)B) break;
        const long long b = bu;

        // ---- Phase 0: stage x and W (float4) -----------------------------
        {
            float4* xs4 = (float4*)(smem + A_OFF);
            const float4* xb4 = (const float4*)(x + b * (long long)(FN * EN));
            #pragma unroll
            for (int it = 0; it < 3; it++) {
                int idx = tid + it * THREADS;
                if (idx < (FN * EN) / 4) xs4[idx] = xb4[idx];
            }
            if (tid < EN)                              // zero pad row f=39
                smem[A_OFF + FN * EN + tid] = 0.f;

            float4* Wi4 = (float4*)(smem + B_OFF);     // [c][17]
            float4* Wj4 = Wi4 + CN * 17;
            const float4* Wg4 = (const float4*)W;
            #pragma unroll
            for (int it = 0; it < 8; it++) {
                int idx = tid + it * THREADS;          // 2048 float4 total
                int c = idx >> 5, q = idx & 31;
                float4 w = Wg4[idx];
                if (q < 16) Wi4[c * 17 + q] = w;
                else        Wj4[c * 17 + (q - 16)] = w;
            }
        }
        __syncthreads();

        // ---- Phase 1: U = x @ Wi^T + b, V = x @ Wj^T  (f32x2) ------------
        const int c  = tid & 63;
        const int fg = tid >> 6;

        unsigned long long au[10], av[10];
        #pragma unroll
        for (int k = 0; k < 10; k++) { au[k] = 0ull; av[k] = 0ull; }

        {
            const ulonglong2* xs2 = (const ulonglong2*)(smem + A_OFF);   // [f][16]
            const ulonglong2* Wi2 = (const ulonglong2*)(smem + B_OFF);   // [c][17]
            const ulonglong2* Wj2 = Wi2 + CN * 17;

            #pragma unroll
            for (int e4 = 0; e4 < 16; e4++) {
                ulonglong2 wi = Wi2[c * 17 + e4];
                ulonglong2 wj = Wj2[c * 17 + e4];
                #pragma unroll
                for (int k = 0; k < 10; k++) {
                    ulonglong2 xv = xs2[(fg + 4 * k) * 16 + e4];  // f=39 zeros
                    FMA_F32X2(au[k], xv.x, wi.x);
                    FMA_F32X2(au[k], xv.y, wi.y);
                    FMA_F32X2(av[k], xv.x, wj.x);
                    FMA_F32X2(av[k], xv.y, wj.y);
                }
            }
        }
        __syncthreads();   // all xs/W reads done; safe to overlay

        // ---- Phase 1b: write Uc/Vc (transposed, stride 41) ---------------
        float* Uc = smem + A_OFF;                 // [c][41]
        float* Vc = smem + B_OFF;                 // [c][41]
        {
            const float bc = __ldg(bias + c);
            #pragma unroll
            for (int k = 0; k < 10; k++) {
                int f = fg + 4 * k;               // f<=39; f=39 lands in pad
                float ulo = __uint_as_float((unsigned)au[k]);
                float uhi = __uint_as_float((unsigned)(au[k] >> 32));
                float vlo = __uint_as_float((unsigned)av[k]);
                float vhi = __uint_as_float((unsigned)(av[k] >> 32));
                Uc[c * 41 + f] = ulo + uhi + bc;  // bias folded into U
                Vc[c * 41 + f] = vlo + vhi;
            }
        }
        __syncthreads();

        // ---- Phase 2: expansion + relu, fused row pairs, register tab ----
        float* outb = out + b * (long long)OUTB;

        #pragma unroll 1
        for (int k = 0; k < 4; k++) {
            const int r  = wrp * 4 + k;           // rows r and r+32 share p0
            const int p0 = (27 * r) & 31;

            // preload the 22-entry aligned tab window into registers
            unsigned tw[22];
            {
                const unsigned* tb = tab + p0 + lane;
                #pragma unroll
                for (int it = 0; it < 22; it++) tw[it] = tb[it * 32];
            }

            const char* bu0 = (const char*)(Uc + r * 41);
            const char* bv0 = (const char*)(Vc + r * 41);
            const char* bu1 = (const char*)(Uc + (r + 32) * 41);
            const char* bv1 = (const char*)(Vc + (r + 32) * 41);
            float* po0 = outb + r * PN;
            float* po1 = outb + (r + 32) * PN;

            // head: p in [0, p0), both rows
            if (lane < p0) {
                unsigned t = tab[lane];
                float u0 = *(const float*)(bu0 + (t & 0xFFFFu));
                float v0 = *(const float*)(bv0 + (t >> 16));
                float u1 = *(const float*)(bu1 + (t & 0xFFFFu));
                float v1 = *(const float*)(bv1 + (t >> 16));
                __stcs(po0 + lane, fmaxf(u0 + v0, 0.f));
                __stcs(po1 + lane, fmaxf(u1 + v1, 0.f));
            }

            // main: 22 warp-iterations, both rows per iteration
            float* q0 = po0 + p0;
            float* q1 = po1 + p0;
            #pragma unroll
            for (int it = 0; it < 22; it++) {
                unsigned t = tw[it];
                unsigned ui = t & 0xFFFFu, vi = t >> 16;
                float u0 = *(const float*)(bu0 + ui);
                float v0 = *(const float*)(bv0 + vi);
                float u1 = *(const float*)(bu1 + ui);
                float v1 = *(const float*)(bv1 + vi);
                __stcs(q0 + it * 32 + lane, fmaxf(u0 + v0, 0.f));
                __stcs(q1 + it * 32 + lane, fmaxf(u1 + v1, 0.f));
            }

            // tail: p in [p0+704, 741), both rows
            int p = p0 + 704 + lane;
            #pragma unroll
            for (int tt = 0; tt < 2; tt++) {
                if (p < PN) {
                    unsigned t = tab[p];
                    float u0 = *(const float*)(bu0 + (t & 0xFFFFu));
                    float v0 = *(const float*)(bv0 + (t >> 16));
                    float u1 = *(const float*)(bu1 + (t & 0xFFFFu));
                    float v1 = *(const float*)(bv1 + (t >> 16));
                    __stcs(po0 + p, fmaxf(u0 + v0, 0.f));
                    __stcs(po1 + p, fmaxf(u1 + v1, 0.f));
                }
                p += 32;
            }
        }
    }
}

extern "C" void kernel_launch(void* const* d_in, const int* in_sizes, int n_in,
                              void* d_out, int out_size)
{
    const float* x    = (const float*)d_in[0];
    const float* W    = (const float*)d_in[1];
    const float* bias = (const float*)d_in[2];
    float* out = (float*)d_out;

    const int B = in_sizes[0] / (FN * EN);   // 2048

    int dev = 0, sms = 148;
    cudaGetDevice(&dev);
    cudaDeviceGetAttribute(&sms, cudaDevAttrMultiProcessorCount, dev);

    cudaFuncSetAttribute(interconv_kernel,
                         cudaFuncAttributeMaxDynamicSharedMemorySize, SMEM_BYTES);

    reset_ctr<<<1, 1>>>();
    interconv_kernel<<<sms * 4, THREADS, SMEM_BYTES>>>(x, W, bias, out, B);
}